// round 7
// baseline (speedup 1.0000x reference)
#include <cuda_runtime.h>

#define T_STEPS 2048
#define BATCH   2048
#define HID     32

typedef unsigned long long u64;

#define S_SIG  (-1.4426950408889634f)   /* -log2(e)   */
#define S_TNH  (-2.8853900817779268f)   /* -2*log2(e) */

// grid/layout constants: 148 CTAs x 320 threads (10 warps).
// Heavy warps (2 batches) sit at wid < Hc (one per SMSP); light warps take 1 batch.
// CTAs 0..123 have 4 heavies, CTAs 124..147 have 3.  4*124 + 3*24 = 568 heavies
// -> batches 0..1135 heavy, 1136..2047 light (912 lights of 1480-568=912 slots).
#define NCTA   148
#define NWARP  10

// ---- packed f32x2 helpers ----
__device__ __forceinline__ u64 ffma2(u64 a, u64 b, u64 c) {
    u64 d;
    asm("fma.rn.f32x2 %0, %1, %2, %3;" : "=l"(d) : "l"(a), "l"(b), "l"(c));
    return d;
}
__device__ __forceinline__ u64 pack2(float lo, float hi) {
    u64 d;
    asm("mov.b64 %0, {%1, %2};" : "=l"(d) : "f"(lo), "f"(hi));
    return d;
}
__device__ __forceinline__ void unpack2(u64 v, float& lo, float& hi) {
    asm("mov.b64 {%0, %1}, %2;" : "=f"(lo), "=f"(hi) : "l"(v));
}
__device__ __forceinline__ float ex2f(float x) {
    float y; asm("ex2.approx.f32 %0, %1;" : "=f"(y) : "f"(x)); return y;
}
__device__ __forceinline__ float rcpf(float x) {
    float y; asm("rcp.approx.f32 %0, %1;" : "=f"(y) : "f"(x)); return y;
}

// predicated stores, no BSSY/BSYNC
__device__ __forceinline__ void stg64_pred(int pred, float* p, float a, float b) {
    asm volatile("{\n\t"
                 ".reg .pred p;\n\t"
                 "setp.ne.u32 p, %0, 0;\n\t"
                 "@p st.global.v2.f32 [%1], {%2, %3};\n\t"
                 "}" :: "r"(pred), "l"(p), "f"(a), "f"(b) : "memory");
}
__device__ __forceinline__ void stg32_pred(int pred, float* p, float a) {
    asm volatile("{\n\t"
                 ".reg .pred p;\n\t"
                 "setp.ne.u32 p, %0, 0;\n\t"
                 "@p st.global.f32 [%1], %2;\n\t"
                 "}" :: "r"(pred), "l"(p), "f"(a) : "memory");
}

__global__ void __launch_bounds__(320, 1) lstm_kernel(
    const float* __restrict__ x,      // [T, B, 1]
    const float* __restrict__ W_ih,   // [4H, 1]
    const float* __restrict__ W_hh,   // [4H, H]
    const float* __restrict__ b_ih,   // [4H]
    const float* __restrict__ b_hh,   // [4H]
    const float* __restrict__ W_out,  // [1, H]
    const float* __restrict__ b_out,  // [1]
    float* __restrict__ out,          // [T*B] outs, then [B*H] hT, then [B*H] cT
    int out_size)
{
    const int lane = threadIdx.x & 31;
    const int wid  = threadIdx.x >> 5;
    const int c    = blockIdx.x;

    const int Hc = (c < 124) ? 4 : 3;                       // heavies in this CTA
    const int heavies_before = (c < 124) ? 4 * c : 496 + 3 * (c - 124);

    // Per-lane weights, pre-scaled per gate (i,f,o: S_SIG; g: S_TNH). Shared by both paths.
    u64 w2[4][16];
    float wih[4], bias[4];
    #pragma unroll
    for (int g = 0; g < 4; g++) {
        const int row = g * 32 + lane;
        const float s = (g == 2) ? S_TNH : S_SIG;
        const float* wr = W_hh + row * HID;
        #pragma unroll
        for (int p = 0; p < 16; p++)
            w2[g][p] = pack2(wr[2 * p] * s, wr[2 * p + 1] * s);
        wih[g]  = W_ih[row] * s;
        bias[g] = (b_ih[row] + b_hh[row]) * s;
    }
    const float wout = W_out[lane];
    const float bout = b_out[0];

    // h broadcast staging: [warp][double-buffer][batch][hidden]
    __shared__ __align__(16) float sh[NWARP][2][2][32];

    const int store_pred = (lane == 0);
    const bool has_state = (out_size >= T_STEPS * BATCH + 2 * BATCH * HID);
    float* hT = out + (size_t)T_STEPS * BATCH;
    float* cT = hT + BATCH * HID;

    if (wid < Hc) {
        // ===================== HEAVY: 2 batches =====================
        const int k  = heavies_before + wid;
        const int b0 = 2 * k;

        float h0 = 0.f, c0 = 0.f, h1 = 0.f, c1 = 0.f;
        float rp0 = 0.f, rp1 = 0.f;

        const float* xp = x + b0;
        float2 xv = *reinterpret_cast<const float2*>(xp);
        float* outp = out + b0;

        #pragma unroll 2
        for (int t = 0; t < T_STEPS; t++) {
            const int buf = t & 1;
            sh[wid][buf][0][lane] = h0;
            sh[wid][buf][1][lane] = h1;

            const float* xpn = (t < T_STEPS - 1) ? (xp + BATCH) : xp;
            float2 xnext = *reinterpret_cast<const float2*>(xpn);
            xp = xpn;

            u64 acc0[4], acc1[4];
            #pragma unroll
            for (int g = 0; g < 4; g++) {
                acc0[g] = pack2(fmaf(xv.x, wih[g], bias[g]), 0.0f);
                acc1[g] = pack2(fmaf(xv.y, wih[g], bias[g]), 0.0f);
            }

            __syncwarp();

            float r0 = rp0, r1 = rp1;
            #pragma unroll
            for (int off = 16; off; off >>= 1) {
                r0 += __shfl_xor_sync(0xffffffffu, r0, off);
                r1 += __shfl_xor_sync(0xffffffffu, r1, off);
            }

            const double2* hp0 = reinterpret_cast<const double2*>(sh[wid][buf][0]);
            const double2* hp1 = reinterpret_cast<const double2*>(sh[wid][buf][1]);
            #pragma unroll
            for (int q = 0; q < 8; q++) {
                double2 v0 = hp0[q], v1 = hp1[q];
                u64 p00 = __double_as_longlong(v0.x), p01 = __double_as_longlong(v0.y);
                u64 p10 = __double_as_longlong(v1.x), p11 = __double_as_longlong(v1.y);
                #pragma unroll
                for (int g = 0; g < 4; g++) {
                    acc0[g] = ffma2(p00, w2[g][2 * q], acc0[g]);
                    acc1[g] = ffma2(p10, w2[g][2 * q], acc1[g]);
                }
                #pragma unroll
                for (int g = 0; g < 4; g++) {
                    acc0[g] = ffma2(p01, w2[g][2 * q + 1], acc0[g]);
                    acc1[g] = ffma2(p11, w2[g][2 * q + 1], acc1[g]);
                }
            }

            stg64_pred(store_pred, outp, r0 + bout, r1 + bout);
            outp += (t > 0) ? BATCH : 0;

            float vi0, vf0, vg0, vo0, vi1, vf1, vg1, vo1;
            {
                float lo, hi;
                unpack2(acc0[0], lo, hi); vi0 = lo + hi;
                unpack2(acc0[1], lo, hi); vf0 = lo + hi;
                unpack2(acc0[2], lo, hi); vg0 = lo + hi;
                unpack2(acc0[3], lo, hi); vo0 = lo + hi;
                unpack2(acc1[0], lo, hi); vi1 = lo + hi;
                unpack2(acc1[1], lo, hi); vf1 = lo + hi;
                unpack2(acc1[2], lo, hi); vg1 = lo + hi;
                unpack2(acc1[3], lo, hi); vo1 = lo + hi;
            }

            float i0g, f0g, o0g, g0g;
            {
                float Ei = ex2f(vi0), Ef = ex2f(vf0), Eg = ex2f(vg0), Eo = ex2f(vo0);
                float Pi = 1.f + Ei, Pf = 1.f + Ef, Pg = 1.f + Eg, Po = 1.f + Eo;
                float Pif = Pi * Pf, Pgo = Pg * Po;
                float R = rcpf(Pif * Pgo);
                float PgoR = Pgo * R, PifR = Pif * R;
                i0g = Pf * PgoR; f0g = Pi * PgoR;
                o0g = PifR * Pg; g0g = fmaf(2.f, PifR * Po, -1.f);
            }
            float i1g, f1g, o1g, g1g;
            {
                float Ei = ex2f(vi1), Ef = ex2f(vf1), Eg = ex2f(vg1), Eo = ex2f(vo1);
                float Pi = 1.f + Ei, Pf = 1.f + Ef, Pg = 1.f + Eg, Po = 1.f + Eo;
                float Pif = Pi * Pf, Pgo = Pg * Po;
                float R = rcpf(Pif * Pgo);
                float PgoR = Pgo * R, PifR = Pif * R;
                i1g = Pf * PgoR; f1g = Pi * PgoR;
                o1g = PifR * Pg; g1g = fmaf(2.f, PifR * Po, -1.f);
            }

            c0 = fmaf(f0g, c0, i0g * g0g);
            c1 = fmaf(f1g, c1, i1g * g1g);

            {
                float a0 = fminf(c0 * S_TNH, 63.f);
                float a1 = fminf(c1 * S_TNH, 63.f);
                float T0 = 1.f + ex2f(a0);
                float T1 = 1.f + ex2f(a1);
                float Rt = rcpf(T0 * T1);
                h0 = o0g * fmaf(2.f, T1 * Rt, -1.f);
                h1 = o1g * fmaf(2.f, T0 * Rt, -1.f);
            }

            rp0 = h0 * wout;
            rp1 = h1 * wout;
            xv = xnext;
        }

        {   // epilogue: out[T-1] (outp already at row T-1)
            float r0 = rp0, r1 = rp1;
            #pragma unroll
            for (int off = 16; off; off >>= 1) {
                r0 += __shfl_xor_sync(0xffffffffu, r0, off);
                r1 += __shfl_xor_sync(0xffffffffu, r1, off);
            }
            stg64_pred(store_pred, outp, r0 + bout, r1 + bout);
        }
        if (has_state) {
            hT[(size_t)(b0 + 0) * HID + lane] = h0;
            hT[(size_t)(b0 + 1) * HID + lane] = h1;
            cT[(size_t)(b0 + 0) * HID + lane] = c0;
            cT[(size_t)(b0 + 1) * HID + lane] = c1;
        }
    } else {
        // ===================== LIGHT: 1 batch =====================
        const int lights_before = NWARP * c - heavies_before;
        const int b = 1136 + lights_before + (wid - Hc);

        float h0 = 0.f, c0 = 0.f, rp0 = 0.f;

        const float* xp = x + b;
        float xv = *xp;
        float* outp = out + b;

        #pragma unroll 2
        for (int t = 0; t < T_STEPS; t++) {
            const int buf = t & 1;
            sh[wid][buf][0][lane] = h0;

            const float* xpn = (t < T_STEPS - 1) ? (xp + BATCH) : xp;
            float xnext = *xpn;
            xp = xpn;

            u64 acc0[4];
            #pragma unroll
            for (int g = 0; g < 4; g++)
                acc0[g] = pack2(fmaf(xv, wih[g], bias[g]), 0.0f);

            __syncwarp();

            float r0 = rp0;
            #pragma unroll
            for (int off = 16; off; off >>= 1)
                r0 += __shfl_xor_sync(0xffffffffu, r0, off);

            const double2* hp0 = reinterpret_cast<const double2*>(sh[wid][buf][0]);
            #pragma unroll
            for (int q = 0; q < 8; q++) {
                double2 v0 = hp0[q];
                u64 p00 = __double_as_longlong(v0.x), p01 = __double_as_longlong(v0.y);
                #pragma unroll
                for (int g = 0; g < 4; g++)
                    acc0[g] = ffma2(p00, w2[g][2 * q], acc0[g]);
                #pragma unroll
                for (int g = 0; g < 4; g++)
                    acc0[g] = ffma2(p01, w2[g][2 * q + 1], acc0[g]);
            }

            stg32_pred(store_pred, outp, r0 + bout);
            outp += (t > 0) ? BATCH : 0;

            float vi0, vf0, vg0, vo0;
            {
                float lo, hi;
                unpack2(acc0[0], lo, hi); vi0 = lo + hi;
                unpack2(acc0[1], lo, hi); vf0 = lo + hi;
                unpack2(acc0[2], lo, hi); vg0 = lo + hi;
                unpack2(acc0[3], lo, hi); vo0 = lo + hi;
            }
            float i0g, f0g, o0g, g0g;
            {
                float Ei = ex2f(vi0), Ef = ex2f(vf0), Eg = ex2f(vg0), Eo = ex2f(vo0);
                float Pi = 1.f + Ei, Pf = 1.f + Ef, Pg = 1.f + Eg, Po = 1.f + Eo;
                float Pif = Pi * Pf, Pgo = Pg * Po;
                float R = rcpf(Pif * Pgo);
                float PgoR = Pgo * R, PifR = Pif * R;
                i0g = Pf * PgoR; f0g = Pi * PgoR;
                o0g = PifR * Pg; g0g = fmaf(2.f, PifR * Po, -1.f);
            }
            c0 = fmaf(f0g, c0, i0g * g0g);
            {
                float a0 = fminf(c0 * S_TNH, 63.f);
                float T0 = 1.f + ex2f(a0);
                h0 = o0g * fmaf(2.f, rcpf(T0), -1.f);
            }
            rp0 = h0 * wout;
            xv = xnext;
        }

        {   // epilogue
            float r0 = rp0;
            #pragma unroll
            for (int off = 16; off; off >>= 1)
                r0 += __shfl_xor_sync(0xffffffffu, r0, off);
            stg32_pred(store_pred, outp, r0 + bout);
        }
        if (has_state) {
            hT[(size_t)b * HID + lane] = h0;
            cT[(size_t)b * HID + lane] = c0;
        }
    }
}

extern "C" void kernel_launch(void* const* d_in, const int* in_sizes, int n_in,
                              void* d_out, int out_size) {
    const float* x     = (const float*)d_in[0];
    const float* W_ih  = (const float*)d_in[1];
    const float* W_hh  = (const float*)d_in[2];
    const float* b_ih  = (const float*)d_in[3];
    const float* b_hh  = (const float*)d_in[4];
    const float* W_out = (const float*)d_in[5];
    const float* b_out = (const float*)d_in[6];
    float* out = (float*)d_out;

    // 148 CTAs x 320 threads: 1480 warps = 568 heavy (2 batches) + 912 light (1 batch),
    // one wave over all 148 SMs, ~2.5 warps/SMSP.
    lstm_kernel<<<NCTA, 320>>>(x, W_ih, W_hh, b_ih, b_hh, W_out, b_out, out, out_size);
}